// round 1
// baseline (speedup 1.0000x reference)
#include <cuda_runtime.h>
#include <cuda_bf16.h>
#include <cstdint>

// Problem constants
#define BWIN   8192
#define NTOK   49
#define CDIM   192
#define HEADS  6
#define HD     32
#define NWMASK 1024
#define MROWS  (BWIN * NTOK)      // 401408
#define QKVC   (3 * CDIM)         // 576

// Scratch (static device globals: allocation-free rule)
__device__ float g_qkv[(size_t)MROWS * QKVC];   // [m][576], c = which*192 + h*32 + d
__device__ float g_att[(size_t)MROWS * CDIM];   // attention output [m][192]

// ---------------- packed f32x2 helpers ----------------
__device__ __forceinline__ unsigned long long pk2(float lo, float hi) {
    unsigned long long r;
    asm("mov.b64 %0, {%1, %2};" : "=l"(r)
        : "r"(__float_as_uint(lo)), "r"(__float_as_uint(hi)));
    return r;
}
__device__ __forceinline__ void upk2(unsigned long long p, float& lo, float& hi) {
    unsigned int l, h;
    asm("mov.b64 {%0, %1}, %2;" : "=r"(l), "=r"(h) : "l"(p));
    lo = __uint_as_float(l);
    hi = __uint_as_float(h);
}
__device__ __forceinline__ void fma2(unsigned long long& acc,
                                     unsigned long long a2,
                                     unsigned long long b2) {
    asm("fma.rn.f32x2 %0, %1, %2, %0;" : "+l"(acc) : "l"(a2), "l"(b2));
}

// ---------------- GEMM: C[m][n] = sum_k A[m][k] * W[n][k] + bias[n] ----------------
// A: [Mrows][K] row-major, W: [Ncols][K] row-major (TN gemm).
// BM=BN=128, BK=16, 256 threads, per-thread 8x8 outputs arranged as 2x2 blocks of 4x4
// (cols/rows split {frag*4, 64+frag*4} for conflict-free LDS.128).
// scaleQ!=0: multiply columns < 192 by hd^-0.5 (fold attention scale into Q).
#define BM 128
#define BN 128
#define BK 16
#define SPAD 4

__global__ __launch_bounds__(256, 2)
void gemm_tn(const float* __restrict__ A, const float* __restrict__ W,
             const float* __restrict__ bias, float* __restrict__ C,
             int Ncols, int K, int scaleQ) {
    __shared__ float As[BK][BM + SPAD];
    __shared__ float Bs[BK][BN + SPAD];

    const int tid = threadIdx.x;
    const int tx = tid & 15;          // n direction (16)
    const int ty = tid >> 4;          // m direction (16)
    const int m0 = blockIdx.x * BM;
    const int n0 = blockIdx.y * BN;

    unsigned long long acc[2][4][2][2];  // [mh][i][nh][jpair]
#pragma unroll
    for (int a = 0; a < 2; a++)
#pragma unroll
        for (int i = 0; i < 4; i++)
#pragma unroll
            for (int b = 0; b < 2; b++) {
                acc[a][i][b][0] = 0ull;
                acc[a][i][b][1] = 0ull;
            }

    for (int kt = 0; kt < K; kt += BK) {
        // Load 128x16 tiles of A and W (512 float4 each, 2 per thread), store transposed.
#pragma unroll
        for (int l = 0; l < 2; l++) {
            int slot = tid + l * 256;
            int row = slot >> 2;          // 0..127
            int c4 = (slot & 3) * 4;      // 0,4,8,12
            float4 av = *(const float4*)(A + (size_t)(m0 + row) * K + kt + c4);
            As[c4 + 0][row] = av.x;
            As[c4 + 1][row] = av.y;
            As[c4 + 2][row] = av.z;
            As[c4 + 3][row] = av.w;
            int nrow = n0 + row;
            float4 bv = make_float4(0.f, 0.f, 0.f, 0.f);
            if (nrow < Ncols)
                bv = *(const float4*)(W + (size_t)nrow * K + kt + c4);
            Bs[c4 + 0][row] = bv.x;
            Bs[c4 + 1][row] = bv.y;
            Bs[c4 + 2][row] = bv.z;
            Bs[c4 + 3][row] = bv.w;
        }
        __syncthreads();

#pragma unroll
        for (int k = 0; k < BK; k++) {
            float4 a0 = *(const float4*)&As[k][ty * 4];
            float4 a1 = *(const float4*)&As[k][64 + ty * 4];
            float4 b0 = *(const float4*)&Bs[k][tx * 4];
            float4 b1 = *(const float4*)&Bs[k][64 + tx * 4];
            unsigned long long bp[2][2];
            bp[0][0] = pk2(b0.x, b0.y);
            bp[0][1] = pk2(b0.z, b0.w);
            bp[1][0] = pk2(b1.x, b1.y);
            bp[1][1] = pk2(b1.z, b1.w);
            float am[2][4] = {{a0.x, a0.y, a0.z, a0.w}, {a1.x, a1.y, a1.z, a1.w}};
#pragma unroll
            for (int mh = 0; mh < 2; mh++)
#pragma unroll
                for (int i = 0; i < 4; i++) {
                    unsigned long long ap = pk2(am[mh][i], am[mh][i]);
#pragma unroll
                    for (int nh = 0; nh < 2; nh++) {
                        fma2(acc[mh][i][nh][0], ap, bp[nh][0]);
                        fma2(acc[mh][i][nh][1], ap, bp[nh][1]);
                    }
                }
        }
        __syncthreads();
    }

    const float sc = 0.17677669529663687f;  // 32^-0.5
#pragma unroll
    for (int mh = 0; mh < 2; mh++)
#pragma unroll
        for (int i = 0; i < 4; i++) {
            int row = m0 + mh * 64 + ty * 4 + i;
            float* crow = C + (size_t)row * Ncols;
#pragma unroll
            for (int nh = 0; nh < 2; nh++)
#pragma unroll
                for (int jp = 0; jp < 2; jp++) {
                    int col = n0 + nh * 64 + tx * 4 + jp * 2;
                    if (col < Ncols) {  // col even, Ncols even -> col+1 valid too
                        float lo, hi;
                        upk2(acc[mh][i][nh][jp], lo, hi);
                        lo += bias[col];
                        hi += bias[col + 1];
                        if (scaleQ && col < CDIM) {  // cols of a pair on same side of 192
                            lo *= sc;
                            hi *= sc;
                        }
                        float2 o2;
                        o2.x = lo;
                        o2.y = hi;
                        *(float2*)(crow + col) = o2;
                    }
                }
        }
}

// ---------------- Fused per-(window, head) attention ----------------
__global__ __launch_bounds__(128)
void attn_kernel(const float* __restrict__ qkv, const float* __restrict__ mask,
                 const float* __restrict__ bias_tab, const int* __restrict__ rel_idx,
                 float* __restrict__ out) {
    __shared__ float q[NTOK][HD];
    __shared__ float kk[NTOK][HD];
    __shared__ float v[NTOK][HD];
    __shared__ float s[NTOK][NTOK + 1];

    const int b = blockIdx.x;
    const int h = blockIdx.y;
    const int tid = threadIdx.x;

    const float* base = qkv + (size_t)b * NTOK * QKVC + h * HD;
    for (int p = tid; p < NTOK * HD; p += 128) {
        int t = p >> 5, d = p & 31;
        const float* rowp = base + (size_t)t * QKVC + d;
        q[t][d] = rowp[0];        // already scaled by hd^-0.5 in gemm
        kk[t][d] = rowp[CDIM];
        v[t][d] = rowp[2 * CDIM];
    }
    __syncthreads();

    const float* mrow = mask + (size_t)(b & (NWMASK - 1)) * NTOK * NTOK;
    for (int p = tid; p < NTOK * NTOK; p += 128) {
        int i = p / NTOK;
        int j = p - i * NTOK;
        float a = 0.f;
#pragma unroll
        for (int d = 0; d < HD; d++) a = fmaf(q[i][d], kk[j][d], a);
        a += bias_tab[rel_idx[p] * HEADS + h] + mrow[p];
        s[i][j] = a;
    }
    __syncthreads();

    if (tid < NTOK) {
        float mx = -1e30f;
#pragma unroll 7
        for (int j = 0; j < NTOK; j++) mx = fmaxf(mx, s[tid][j]);
        float sum = 0.f;
#pragma unroll 7
        for (int j = 0; j < NTOK; j++) {
            float e = __expf(s[tid][j] - mx);
            s[tid][j] = e;
            sum += e;
        }
        float inv = 1.f / sum;
#pragma unroll 7
        for (int j = 0; j < NTOK; j++) s[tid][j] *= inv;
    }
    __syncthreads();

    float* obase = out + (size_t)b * NTOK * CDIM + h * HD;
    for (int p = tid; p < NTOK * HD; p += 128) {
        int i = p >> 5, d = p & 31;
        float a = 0.f;
#pragma unroll 7
        for (int j = 0; j < NTOK; j++) a = fmaf(s[i][j], v[j][d], a);
        obase[(size_t)i * CDIM + d] = a;
    }
}

// ---------------- launch ----------------
extern "C" void kernel_launch(void* const* d_in, const int* in_sizes, int n_in,
                              void* d_out, int out_size) {
    const float* x        = (const float*)d_in[0];  // [8192,7,7,192]
    const float* mask     = (const float*)d_in[1];  // [1024,49,49]
    const float* qkv_w    = (const float*)d_in[2];  // [576,192]
    const float* qkv_b    = (const float*)d_in[3];  // [576]
    const float* proj_w   = (const float*)d_in[4];  // [192,192]
    const float* proj_b   = (const float*)d_in[5];  // [192]
    const float* bias_tab = (const float*)d_in[6];  // [169,6]
    const int*   rel_idx  = (const int*)d_in[7];    // [49,49]
    float* out = (float*)d_out;

    void* qkv_p = nullptr;
    void* att_p = nullptr;
    cudaGetSymbolAddress(&qkv_p, g_qkv);
    cudaGetSymbolAddress(&att_p, g_att);
    float* qkv = (float*)qkv_p;
    float* att = (float*)att_p;

    // 1) QKV projection (+bias, fold Q scale): [401408,192] x [576,192]^T
    dim3 g1(MROWS / BM, (QKVC + BN - 1) / BN);  // 3136 x 5
    gemm_tn<<<g1, 256>>>(x, qkv_w, qkv_b, qkv, QKVC, CDIM, 1);

    // 2) Window attention per (window, head)
    dim3 g2(BWIN, HEADS);
    attn_kernel<<<g2, 128>>>(qkv, mask, bias_tab, rel_idx, att);

    // 3) Output projection: [401408,192] x [192,192]^T
    dim3 g3(MROWS / BM, (CDIM + BN - 1) / BN);  // 3136 x 2
    gemm_tn<<<g3, 256>>>(att, proj_w, proj_b, out, CDIM, CDIM, 0);
}

// round 6
// speedup vs baseline: 1.5220x; 1.5220x over previous
#include <cuda_runtime.h>
#include <cuda_bf16.h>
#include <cstdint>

// Problem constants
#define BWIN   8192
#define NTOK   49
#define CDIM   192
#define HEADS  6
#define HD     32
#define NWMASK 1024
#define MROWS  (BWIN * NTOK)      // 401408
#define QKVC   (3 * CDIM)         // 576

// Scratch (static device globals: allocation-free rule)
__device__ float g_qkv[(size_t)MROWS * QKVC];   // [m][576], c = which*192 + h*32 + d
__device__ float g_att[(size_t)MROWS * CDIM];   // attention output [m][192]

// ---------------- packed f32x2 helpers ----------------
__device__ __forceinline__ unsigned long long pk2(float lo, float hi) {
    unsigned long long r;
    asm("mov.b64 %0, {%1, %2};" : "=l"(r)
        : "r"(__float_as_uint(lo)), "r"(__float_as_uint(hi)));
    return r;
}
__device__ __forceinline__ void upk2(unsigned long long p, float& lo, float& hi) {
    unsigned int l, h;
    asm("mov.b64 {%0, %1}, %2;" : "=r"(l), "=r"(h) : "l"(p));
    lo = __uint_as_float(l);
    hi = __uint_as_float(h);
}
__device__ __forceinline__ void fma2(unsigned long long& acc,
                                     unsigned long long a2,
                                     unsigned long long b2) {
    asm("fma.rn.f32x2 %0, %1, %2, %0;" : "+l"(acc) : "l"(a2), "l"(b2));
}

// ---------------- GEMM: C[m][n] = sum_k A[m][k] * W[n][k] + bias[n] ----------------
// Identical to Round-1 benched version (fma=67.3%, passed).
#define BM 128
#define BN 128
#define BK 16
#define SPAD 4

__global__ __launch_bounds__(256, 2)
void gemm_tn(const float* __restrict__ A, const float* __restrict__ W,
             const float* __restrict__ bias, float* __restrict__ C,
             int Ncols, int K, int scaleQ) {
    __shared__ float As[BK][BM + SPAD];
    __shared__ float Bs[BK][BN + SPAD];

    const int tid = threadIdx.x;
    const int tx = tid & 15;          // n direction (16)
    const int ty = tid >> 4;          // m direction (16)
    const int m0 = blockIdx.x * BM;
    const int n0 = blockIdx.y * BN;

    unsigned long long acc[2][4][2][2];  // [mh][i][nh][jpair]
#pragma unroll
    for (int a = 0; a < 2; a++)
#pragma unroll
        for (int i = 0; i < 4; i++)
#pragma unroll
            for (int b = 0; b < 2; b++) {
                acc[a][i][b][0] = 0ull;
                acc[a][i][b][1] = 0ull;
            }

    for (int kt = 0; kt < K; kt += BK) {
#pragma unroll
        for (int l = 0; l < 2; l++) {
            int slot = tid + l * 256;
            int row = slot >> 2;          // 0..127
            int c4 = (slot & 3) * 4;      // 0,4,8,12
            float4 av = *(const float4*)(A + (size_t)(m0 + row) * K + kt + c4);
            As[c4 + 0][row] = av.x;
            As[c4 + 1][row] = av.y;
            As[c4 + 2][row] = av.z;
            As[c4 + 3][row] = av.w;
            int nrow = n0 + row;
            float4 bv = make_float4(0.f, 0.f, 0.f, 0.f);
            if (nrow < Ncols)
                bv = *(const float4*)(W + (size_t)nrow * K + kt + c4);
            Bs[c4 + 0][row] = bv.x;
            Bs[c4 + 1][row] = bv.y;
            Bs[c4 + 2][row] = bv.z;
            Bs[c4 + 3][row] = bv.w;
        }
        __syncthreads();

#pragma unroll
        for (int k = 0; k < BK; k++) {
            float4 a0 = *(const float4*)&As[k][ty * 4];
            float4 a1 = *(const float4*)&As[k][64 + ty * 4];
            float4 b0 = *(const float4*)&Bs[k][tx * 4];
            float4 b1 = *(const float4*)&Bs[k][64 + tx * 4];
            unsigned long long bp[2][2];
            bp[0][0] = pk2(b0.x, b0.y);
            bp[0][1] = pk2(b0.z, b0.w);
            bp[1][0] = pk2(b1.x, b1.y);
            bp[1][1] = pk2(b1.z, b1.w);
            float am[2][4] = {{a0.x, a0.y, a0.z, a0.w}, {a1.x, a1.y, a1.z, a1.w}};
#pragma unroll
            for (int mh = 0; mh < 2; mh++)
#pragma unroll
                for (int i = 0; i < 4; i++) {
                    unsigned long long ap = pk2(am[mh][i], am[mh][i]);
#pragma unroll
                    for (int nh = 0; nh < 2; nh++) {
                        fma2(acc[mh][i][nh][0], ap, bp[nh][0]);
                        fma2(acc[mh][i][nh][1], ap, bp[nh][1]);
                    }
                }
        }
        __syncthreads();
    }

    const float sc = 0.17677669529663687f;  // 32^-0.5
#pragma unroll
    for (int mh = 0; mh < 2; mh++)
#pragma unroll
        for (int i = 0; i < 4; i++) {
            int row = m0 + mh * 64 + ty * 4 + i;
            float* crow = C + (size_t)row * Ncols;
#pragma unroll
            for (int nh = 0; nh < 2; nh++)
#pragma unroll
                for (int jp = 0; jp < 2; jp++) {
                    int col = n0 + nh * 64 + tx * 4 + jp * 2;
                    if (col < Ncols) {
                        float lo, hi;
                        upk2(acc[mh][i][nh][jp], lo, hi);
                        lo += bias[col];
                        hi += bias[col + 1];
                        if (scaleQ && col < CDIM) {
                            lo *= sc;
                            hi *= sc;
                        }
                        float2 o2;
                        o2.x = lo;
                        o2.y = hi;
                        *(float2*)(crow + col) = o2;
                    }
                }
        }
}

// ---------------- Fused per-(window, head) attention ----------------
// CHANGE vs R1: K stored transposed (kt[d][j], pitch 50) -> QK^T inner loop
// loads are lane-consecutive in j => conflict-free (was 32-way conflicted).
__global__ __launch_bounds__(128)
void attn_kernel(const float* __restrict__ qkv, const float* __restrict__ mask,
                 const float* __restrict__ bias_tab, const int* __restrict__ rel_idx,
                 float* __restrict__ out) {
    __shared__ float q[NTOK][HD];
    __shared__ float kt[HD][NTOK + 1];
    __shared__ float v[NTOK][HD];
    __shared__ float s[NTOK][NTOK + 1];

    const int b = blockIdx.x;
    const int h = blockIdx.y;
    const int tid = threadIdx.x;

    const float* base = qkv + (size_t)b * NTOK * QKVC + h * HD;
    for (int p = tid; p < NTOK * HD; p += 128) {
        int t = p >> 5, d = p & 31;
        const float* rowp = base + (size_t)t * QKVC + d;
        q[t][d] = rowp[0];        // Q scale folded in gemm epilogue
        kt[d][t] = rowp[CDIM];    // transposed
        v[t][d] = rowp[2 * CDIM];
    }
    __syncthreads();

    const float* mrow = mask + (size_t)(b & (NWMASK - 1)) * NTOK * NTOK;
    for (int p = tid; p < NTOK * NTOK; p += 128) {
        int i = p / NTOK;
        int j = p - i * NTOK;
        float a = 0.f;
#pragma unroll
        for (int d = 0; d < HD; d++) a = fmaf(q[i][d], kt[d][j], a);
        a += __ldg(bias_tab + rel_idx[p] * HEADS + h) + mrow[p];
        s[i][j] = a;
    }
    __syncthreads();

    if (tid < NTOK) {
        float mx = -1e30f;
#pragma unroll 7
        for (int j = 0; j < NTOK; j++) mx = fmaxf(mx, s[tid][j]);
        float sum = 0.f;
#pragma unroll 7
        for (int j = 0; j < NTOK; j++) {
            float e = __expf(s[tid][j] - mx);
            s[tid][j] = e;
            sum += e;
        }
        float inv = 1.f / sum;
#pragma unroll 7
        for (int j = 0; j < NTOK; j++) s[tid][j] *= inv;
    }
    __syncthreads();

    float* obase = out + (size_t)b * NTOK * CDIM + h * HD;
    for (int p = tid; p < NTOK * HD; p += 128) {
        int i = p >> 5, d = p & 31;
        float a = 0.f;
#pragma unroll 7
        for (int j = 0; j < NTOK; j++) a = fmaf(s[i][j], v[j][d], a);
        obase[(size_t)i * CDIM + d] = a;
    }
}

// ---------------- launch ----------------
extern "C" void kernel_launch(void* const* d_in, const int* in_sizes, int n_in,
                              void* d_out, int out_size) {
    const float* x        = (const float*)d_in[0];  // [8192,7,7,192]
    const float* mask     = (const float*)d_in[1];  // [1024,49,49]
    const float* qkv_w    = (const float*)d_in[2];  // [576,192]
    const float* qkv_b    = (const float*)d_in[3];  // [576]
    const float* proj_w   = (const float*)d_in[4];  // [192,192]
    const float* proj_b   = (const float*)d_in[5];  // [192]
    const float* bias_tab = (const float*)d_in[6];  // [169,6]
    const int*   rel_idx  = (const int*)d_in[7];    // [49,49]
    float* out = (float*)d_out;

    void* qkv_p = nullptr;
    void* att_p = nullptr;
    cudaGetSymbolAddress(&qkv_p, g_qkv);
    cudaGetSymbolAddress(&att_p, g_att);
    float* qkv = (float*)qkv_p;
    float* att = (float*)att_p;

    // 1) QKV projection (+bias, fold Q scale): [401408,192] x [576,192]^T
    dim3 g1(MROWS / BM, (QKVC + BN - 1) / BN);  // 3136 x 5
    gemm_tn<<<g1, 256>>>(x, qkv_w, qkv_b, qkv, QKVC, CDIM, 1);

    // 2) Window attention per (window, head)
    dim3 g2(BWIN, HEADS);
    attn_kernel<<<g2, 128>>>(qkv, mask, bias_tab, rel_idx, att);

    // 3) Output projection: [401408,192] x [192,192]^T
    dim3 g3(MROWS / BM, (CDIM + BN - 1) / BN);  // 3136 x 2
    gemm_tn<<<g3, 256>>>(att, proj_w, proj_b, out, CDIM, CDIM, 0);
}

// round 7
// speedup vs baseline: 2.1540x; 1.4152x over previous
#include <cuda_runtime.h>
#include <cuda_bf16.h>
#include <cstdint>

// ---------------- Problem constants ----------------
#define BWIN   8192
#define NTOK   49
#define CDIM   192
#define HEADS  6
#define NWMASK 1024
#define HD     32
#define MROWS  (BWIN * NTOK)      // 401408
#define QKVC   (3 * CDIM)        // 576
#define KSPLIT 384               // split bf16: [hi 192 | lo 192]

// smem: A 128 rows x 784B (384 bf16 + pad), W 64 rows x 784B
#define AROWB   784
#define SM_W_OFF (128 * AROWB)
#define SMEM_BYTES (128 * AROWB + 64 * AROWB)   // 150528

// ---------------- Scratch ----------------
__device__ float         g_qkv[(size_t)MROWS * QKVC];   // qkv fp32 (Q pre-scaled)
__device__ float         g_att[(size_t)MROWS * CDIM];   // attention out fp32
__device__ __nv_bfloat16 g_wqs[(size_t)QKVC * KSPLIT];  // qkv_w split
__device__ __nv_bfloat16 g_wps[(size_t)CDIM * KSPLIT];  // proj_w split

// ---------------- helpers ----------------
__device__ __forceinline__ uint32_t smem_u32(const void* p) {
    uint32_t a;
    asm("{ .reg .u64 t; cvta.to.shared.u64 t, %1; cvt.u32.u64 %0, t; }"
        : "=r"(a) : "l"(p));
    return a;
}
__device__ __forceinline__ void ldsm_x4(uint32_t* r, uint32_t addr) {
    asm volatile("ldmatrix.sync.aligned.m8n8.x4.shared.b16 {%0,%1,%2,%3}, [%4];"
                 : "=r"(r[0]), "=r"(r[1]), "=r"(r[2]), "=r"(r[3]) : "r"(addr));
}
__device__ __forceinline__ void mma_bf16(float* d, const uint32_t* a,
                                         uint32_t b0, uint32_t b1) {
    asm volatile(
        "mma.sync.aligned.m16n8k16.row.col.f32.bf16.bf16.f32 "
        "{%0,%1,%2,%3},{%4,%5,%6,%7},{%8,%9},{%0,%1,%2,%3};"
        : "+f"(d[0]), "+f"(d[1]), "+f"(d[2]), "+f"(d[3])
        : "r"(a[0]), "r"(a[1]), "r"(a[2]), "r"(a[3]), "r"(b0), "r"(b1));
}
__device__ __forceinline__ uint32_t pkbf(__nv_bfloat16 a, __nv_bfloat16 b) {
    __nv_bfloat162 t(a, b);
    return *(uint32_t*)&t;
}

// ---------------- split fp32 -> [hi|lo] bf16 (weights) ----------------
__global__ void split_f32_kernel(const float* __restrict__ in,
                                 __nv_bfloat16* __restrict__ out, long total4) {
    long i = (long)blockIdx.x * blockDim.x + threadIdx.x;
    if (i >= total4) return;
    long r = i / 48;
    int c4 = (int)(i - r * 48) * 4;
    float4 v = ((const float4*)in)[i];
    __nv_bfloat16 h0 = __float2bfloat16(v.x), h1 = __float2bfloat16(v.y);
    __nv_bfloat16 h2 = __float2bfloat16(v.z), h3 = __float2bfloat16(v.w);
    __nv_bfloat16 l0 = __float2bfloat16(v.x - __bfloat162float(h0));
    __nv_bfloat16 l1 = __float2bfloat16(v.y - __bfloat162float(h1));
    __nv_bfloat16 l2 = __float2bfloat16(v.z - __bfloat162float(h2));
    __nv_bfloat16 l3 = __float2bfloat16(v.w - __bfloat162float(h3));
    uint2 hp; hp.x = pkbf(h0, h1); hp.y = pkbf(h2, h3);
    uint2 lp; lp.x = pkbf(l0, l1); lp.y = pkbf(l2, l3);
    *(uint2*)(out + r * KSPLIT + c4) = hp;
    *(uint2*)(out + r * KSPLIT + 192 + c4) = lp;
}

// ---------------- mma.sync GEMM ----------------
// C[m][n] = sum_k A[m][k] * W[n][k] + bias[n]; split-bf16 3-pass chain, K_eff=576.
// A is fp32 [M][192], converted to split bf16 in-kernel; tile resident in smem
// across all n-tiles (A read from DRAM exactly once).
__global__ __launch_bounds__(256)
void gemm_mma(const float* __restrict__ Ain, const __nv_bfloat16* __restrict__ Wsp,
              const float* __restrict__ bias, float* __restrict__ C,
              int Ntiles, int do_scale) {
    extern __shared__ __align__(16) unsigned char sm[];
    const int tid = threadIdx.x;
    const size_t m0 = (size_t)blockIdx.x * 128;
    const int P = Ntiles * 64;

    // ---- stage A: fp32 -> split bf16 into smem ----
    {
        const float4* src = (const float4*)(Ain + m0 * CDIM);
#pragma unroll
        for (int t = 0; t < 24; t++) {
            int s = tid + t * 256;
            int row = s / 48, j = s - row * 48;     // j: float4 index in row
            float4 v = src[row * 48 + j];
            __nv_bfloat16 h0 = __float2bfloat16(v.x), h1 = __float2bfloat16(v.y);
            __nv_bfloat16 h2 = __float2bfloat16(v.z), h3 = __float2bfloat16(v.w);
            __nv_bfloat16 l0 = __float2bfloat16(v.x - __bfloat162float(h0));
            __nv_bfloat16 l1 = __float2bfloat16(v.y - __bfloat162float(h1));
            __nv_bfloat16 l2 = __float2bfloat16(v.z - __bfloat162float(h2));
            __nv_bfloat16 l3 = __float2bfloat16(v.w - __bfloat162float(h3));
            uint2 hp; hp.x = pkbf(h0, h1); hp.y = pkbf(h2, h3);
            uint2 lp; lp.x = pkbf(l0, l1); lp.y = pkbf(l2, l3);
            *(uint2*)(sm + row * AROWB + j * 8) = hp;
            *(uint2*)(sm + row * AROWB + 384 + j * 8) = lp;
        }
    }

    const uint32_t sAu = smem_u32(sm);
    const uint32_t sWu = sAu + SM_W_OFF;
    const int wid = tid >> 5, l = tid & 31;
    const int wm = (wid >> 1) * 32;   // 0,32,64,96
    const int wn = (wid & 1) * 32;    // 0,32
    // ldmatrix lane bases (A: m16k16 tiles; B: n16k16 tiles)
    const uint32_t aBase = sAu +
        (uint32_t)((wm + (l & 7) + ((l >> 3) & 1) * 8) * AROWB + (((l >> 4) & 1) * 8) * 2);
    const uint32_t bBase = sWu +
        (uint32_t)((wn + (l & 7) + ((l >> 4) & 1) * 8) * AROWB + (((l >> 3) & 1) * 8) * 2);

    const float sc = 0.17677669529663687f;  // 32^-0.5

    for (int nt = 0; nt < Ntiles; nt++) {
        __syncthreads();   // protect W slab (and first-iter A stores)
        {   // load W rows [nt*64, nt*64+64) split bf16 -> smem
            const uint4* wsrc = (const uint4*)Wsp + (size_t)nt * 64 * 48;
#pragma unroll
            for (int t = 0; t < 12; t++) {
                int s = tid + t * 256;
                int row = s / 48, j = s - row * 48;
                *(uint4*)(sm + SM_W_OFF + row * AROWB + j * 16) = wsrc[row * 48 + j];
            }
        }
        __syncthreads();

        float d[2][4][4];
#pragma unroll
        for (int mi = 0; mi < 2; mi++)
#pragma unroll
            for (int ni = 0; ni < 4; ni++)
#pragma unroll
                for (int e = 0; e < 4; e++) d[mi][ni][e] = 0.f;

        // 3 phases: (Aoff,Woff) = (hi,hi), (hi,lo), (lo,hi); 12 k16-steps each
#pragma unroll
        for (int ph = 0; ph < 3; ph++) {
            const uint32_t ab0 = aBase + (ph == 2 ? 384u : 0u);
            const uint32_t bb0 = bBase + (ph == 1 ? 384u : 0u);
#pragma unroll
            for (int ks = 0; ks < 12; ks++) {
                uint32_t a0[4], a1[4], br0[4], br1[4];
                ldsm_x4(a0, ab0 + ks * 32);
                ldsm_x4(a1, ab0 + ks * 32 + 16 * AROWB);
                ldsm_x4(br0, bb0 + ks * 32);
                ldsm_x4(br1, bb0 + ks * 32 + 16 * AROWB);
                mma_bf16(d[0][0], a0, br0[0], br0[1]);
                mma_bf16(d[0][1], a0, br0[2], br0[3]);
                mma_bf16(d[0][2], a0, br1[0], br1[1]);
                mma_bf16(d[0][3], a0, br1[2], br1[3]);
                mma_bf16(d[1][0], a1, br0[0], br0[1]);
                mma_bf16(d[1][1], a1, br0[2], br0[3]);
                mma_bf16(d[1][2], a1, br1[0], br1[1]);
                mma_bf16(d[1][3], a1, br1[2], br1[3]);
            }
        }

        // epilogue: regs -> gmem (bias, optional Q scale)
#pragma unroll
        for (int mi = 0; mi < 2; mi++)
#pragma unroll
            for (int ni = 0; ni < 4; ni++) {
                size_t gr = m0 + wm + mi * 16 + (l >> 2);
                int gc = nt * 64 + wn + ni * 8 + (l & 3) * 2;
                float b0v = __ldg(bias + gc), b1v = __ldg(bias + gc + 1);
                float v0 = d[mi][ni][0] + b0v, v1 = d[mi][ni][1] + b1v;
                float v2 = d[mi][ni][2] + b0v, v3 = d[mi][ni][3] + b1v;
                if (do_scale && gc < CDIM) { v0 *= sc; v1 *= sc; v2 *= sc; v3 *= sc; }
                float2 o0; o0.x = v0; o0.y = v1;
                float2 o1; o1.x = v2; o1.y = v3;
                *(float2*)&C[gr * P + gc] = o0;
                *(float2*)&C[(gr + 8) * P + gc] = o1;
            }
    }
}

// ---------------- Fused per-(window, head) attention ----------------
// Byte-identical to Round-6 passing version (K transposed, conflict-free).
__global__ __launch_bounds__(128)
void attn_kernel(const float* __restrict__ qkv, const float* __restrict__ mask,
                 const float* __restrict__ bias_tab, const int* __restrict__ rel_idx,
                 float* __restrict__ out) {
    __shared__ float q[NTOK][HD];
    __shared__ float kt[HD][NTOK + 1];
    __shared__ float v[NTOK][HD];
    __shared__ float s[NTOK][NTOK + 1];

    const int b = blockIdx.x;
    const int h = blockIdx.y;
    const int tid = threadIdx.x;

    const float* base = qkv + (size_t)b * NTOK * QKVC + h * HD;
    for (int p = tid; p < NTOK * HD; p += 128) {
        int t = p >> 5, d = p & 31;
        const float* rowp = base + (size_t)t * QKVC + d;
        q[t][d] = rowp[0];        // Q scale folded in gemm epilogue
        kt[d][t] = rowp[CDIM];    // transposed
        v[t][d] = rowp[2 * CDIM];
    }
    __syncthreads();

    const float* mrow = mask + (size_t)(b & (NWMASK - 1)) * NTOK * NTOK;
    for (int p = tid; p < NTOK * NTOK; p += 128) {
        int i = p / NTOK;
        int j = p - i * NTOK;
        float a = 0.f;
#pragma unroll
        for (int d = 0; d < HD; d++) a = fmaf(q[i][d], kt[d][j], a);
        a += __ldg(bias_tab + rel_idx[p] * HEADS + h) + mrow[p];
        s[i][j] = a;
    }
    __syncthreads();

    if (tid < NTOK) {
        float mx = -1e30f;
#pragma unroll 7
        for (int j = 0; j < NTOK; j++) mx = fmaxf(mx, s[tid][j]);
        float sum = 0.f;
#pragma unroll 7
        for (int j = 0; j < NTOK; j++) {
            float e = __expf(s[tid][j] - mx);
            s[tid][j] = e;
            sum += e;
        }
        float inv = 1.f / sum;
#pragma unroll 7
        for (int j = 0; j < NTOK; j++) s[tid][j] *= inv;
    }
    __syncthreads();

    float* obase = out + (size_t)b * NTOK * CDIM + h * HD;
    for (int p = tid; p < NTOK * HD; p += 128) {
        int i = p >> 5, d = p & 31;
        float a = 0.f;
#pragma unroll 7
        for (int j = 0; j < NTOK; j++) a = fmaf(s[i][j], v[j][d], a);
        obase[(size_t)i * CDIM + d] = a;
    }
}

// ---------------- launch ----------------
extern "C" void kernel_launch(void* const* d_in, const int* in_sizes, int n_in,
                              void* d_out, int out_size) {
    const float* x        = (const float*)d_in[0];  // [8192,7,7,192]
    const float* mask     = (const float*)d_in[1];  // [1024,49,49]
    const float* qkv_w    = (const float*)d_in[2];  // [576,192]
    const float* qkv_b    = (const float*)d_in[3];  // [576]
    const float* proj_w   = (const float*)d_in[4];  // [192,192]
    const float* proj_b   = (const float*)d_in[5];  // [192]
    const float* bias_tab = (const float*)d_in[6];  // [169,6]
    const int*   rel_idx  = (const int*)d_in[7];    // [49,49]
    float* out = (float*)d_out;

    void *qkv_p, *att_p, *wqs_p, *wps_p;
    cudaGetSymbolAddress(&qkv_p, g_qkv);
    cudaGetSymbolAddress(&att_p, g_att);
    cudaGetSymbolAddress(&wqs_p, g_wqs);
    cudaGetSymbolAddress(&wps_p, g_wps);
    float* qkv = (float*)qkv_p;
    float* att = (float*)att_p;
    __nv_bfloat16* wqs = (__nv_bfloat16*)wqs_p;
    __nv_bfloat16* wps = (__nv_bfloat16*)wps_p;

    cudaFuncSetAttribute(gemm_mma, cudaFuncAttributeMaxDynamicSharedMemorySize,
                         SMEM_BYTES);

    // 0) split weights
    split_f32_kernel<<<(QKVC * 48 + 255) / 256, 256>>>(qkv_w, wqs, QKVC * 48);
    split_f32_kernel<<<(CDIM * 48 + 255) / 256, 256>>>(proj_w, wps, CDIM * 48);

    // 1) QKV projection (+bias, fold Q scale)
    gemm_mma<<<MROWS / 128, 256, SMEM_BYTES>>>(x, wqs, qkv_b, qkv, 9, 1);

    // 2) Window attention (fp32, proven)
    {
        dim3 g(BWIN, HEADS);
        attn_kernel<<<g, 128>>>(qkv, mask, bias_tab, rel_idx, att);
    }

    // 3) Output projection -> d_out
    gemm_mma<<<MROWS / 128, 256, SMEM_BYTES>>>(att, wps, proj_b, out, 3, 0);
}

// round 8
// speedup vs baseline: 3.2108x; 1.4907x over previous
#include <cuda_runtime.h>
#include <cuda_bf16.h>
#include <cstdint>

// ---------------- Problem constants ----------------
#define BWIN   8192
#define NTOK   49
#define CDIM   192
#define HEADS  6
#define NWMASK 1024
#define HD     32
#define MROWS  (BWIN * NTOK)      // 401408
#define QKVC   (3 * CDIM)        // 576
#define KSPLIT 384               // split bf16: [hi 192 | lo 192]
#define NN     (NTOK * NTOK)     // 2401

// smem: A 128 rows x 784B (384 bf16 + pad), W 64 rows x 784B
#define AROWB   784
#define SM_W_OFF (128 * AROWB)
#define SMEM_BYTES (128 * AROWB + 64 * AROWB)   // 150528

// ---------------- Scratch ----------------
__device__ float         g_qkv[(size_t)MROWS * QKVC];   // qkv fp32 (Q pre-scaled)
__device__ float         g_att[(size_t)MROWS * CDIM];   // attention out fp32
__device__ __nv_bfloat16 g_wqs[(size_t)QKVC * KSPLIT];  // qkv_w split
__device__ __nv_bfloat16 g_wps[(size_t)CDIM * KSPLIT];  // proj_w split
__device__ float         g_biash[HEADS * NN];           // bias pre-gathered per head

// ---------------- helpers ----------------
__device__ __forceinline__ uint32_t smem_u32(const void* p) {
    uint32_t a;
    asm("{ .reg .u64 t; cvta.to.shared.u64 t, %1; cvt.u32.u64 %0, t; }"
        : "=r"(a) : "l"(p));
    return a;
}
__device__ __forceinline__ void ldsm_x4(uint32_t* r, uint32_t addr) {
    asm volatile("ldmatrix.sync.aligned.m8n8.x4.shared.b16 {%0,%1,%2,%3}, [%4];"
                 : "=r"(r[0]), "=r"(r[1]), "=r"(r[2]), "=r"(r[3]) : "r"(addr));
}
__device__ __forceinline__ void mma_bf16(float* d, const uint32_t* a,
                                         uint32_t b0, uint32_t b1) {
    asm volatile(
        "mma.sync.aligned.m16n8k16.row.col.f32.bf16.bf16.f32 "
        "{%0,%1,%2,%3},{%4,%5,%6,%7},{%8,%9},{%0,%1,%2,%3};"
        : "+f"(d[0]), "+f"(d[1]), "+f"(d[2]), "+f"(d[3])
        : "r"(a[0]), "r"(a[1]), "r"(a[2]), "r"(a[3]), "r"(b0), "r"(b1));
}
__device__ __forceinline__ uint32_t pkbf(__nv_bfloat16 a, __nv_bfloat16 b) {
    __nv_bfloat162 t(a, b);
    return *(uint32_t*)&t;
}

// ---------------- split fp32 -> [hi|lo] bf16 (weights) ----------------
__global__ void split_f32_kernel(const float* __restrict__ in,
                                 __nv_bfloat16* __restrict__ out, long total4) {
    long i = (long)blockIdx.x * blockDim.x + threadIdx.x;
    if (i >= total4) return;
    long r = i / 48;
    int c4 = (int)(i - r * 48) * 4;
    float4 v = ((const float4*)in)[i];
    __nv_bfloat16 h0 = __float2bfloat16(v.x), h1 = __float2bfloat16(v.y);
    __nv_bfloat16 h2 = __float2bfloat16(v.z), h3 = __float2bfloat16(v.w);
    __nv_bfloat16 l0 = __float2bfloat16(v.x - __bfloat162float(h0));
    __nv_bfloat16 l1 = __float2bfloat16(v.y - __bfloat162float(h1));
    __nv_bfloat16 l2 = __float2bfloat16(v.z - __bfloat162float(h2));
    __nv_bfloat16 l3 = __float2bfloat16(v.w - __bfloat162float(h3));
    uint2 hp; hp.x = pkbf(h0, h1); hp.y = pkbf(h2, h3);
    uint2 lp; lp.x = pkbf(l0, l1); lp.y = pkbf(l2, l3);
    *(uint2*)(out + r * KSPLIT + c4) = hp;
    *(uint2*)(out + r * KSPLIT + 192 + c4) = lp;
}

// ---------------- pre-gather relative-position bias per head ----------------
__global__ void bias_expand_kernel(const float* __restrict__ bias_tab,
                                   const int* __restrict__ rel_idx,
                                   float* __restrict__ out) {
    int t = blockIdx.x * blockDim.x + threadIdx.x;
    if (t >= HEADS * NN) return;
    int h = t / NN, p = t - h * NN;
    out[t] = bias_tab[rel_idx[p] * HEADS + h];
}

// ---------------- mma.sync GEMM (unchanged from R7) ----------------
__global__ __launch_bounds__(256)
void gemm_mma(const float* __restrict__ Ain, const __nv_bfloat16* __restrict__ Wsp,
              const float* __restrict__ bias, float* __restrict__ C,
              int Ntiles, int do_scale) {
    extern __shared__ __align__(16) unsigned char sm[];
    const int tid = threadIdx.x;
    const size_t m0 = (size_t)blockIdx.x * 128;
    const int P = Ntiles * 64;

    {
        const float4* src = (const float4*)(Ain + m0 * CDIM);
#pragma unroll
        for (int t = 0; t < 24; t++) {
            int s = tid + t * 256;
            int row = s / 48, j = s - row * 48;
            float4 v = src[row * 48 + j];
            __nv_bfloat16 h0 = __float2bfloat16(v.x), h1 = __float2bfloat16(v.y);
            __nv_bfloat16 h2 = __float2bfloat16(v.z), h3 = __float2bfloat16(v.w);
            __nv_bfloat16 l0 = __float2bfloat16(v.x - __bfloat162float(h0));
            __nv_bfloat16 l1 = __float2bfloat16(v.y - __bfloat162float(h1));
            __nv_bfloat16 l2 = __float2bfloat16(v.z - __bfloat162float(h2));
            __nv_bfloat16 l3 = __float2bfloat16(v.w - __bfloat162float(h3));
            uint2 hp; hp.x = pkbf(h0, h1); hp.y = pkbf(h2, h3);
            uint2 lp; lp.x = pkbf(l0, l1); lp.y = pkbf(l2, l3);
            *(uint2*)(sm + row * AROWB + j * 8) = hp;
            *(uint2*)(sm + row * AROWB + 384 + j * 8) = lp;
        }
    }

    const uint32_t sAu = smem_u32(sm);
    const uint32_t sWu = sAu + SM_W_OFF;
    const int wid = tid >> 5, l = tid & 31;
    const int wm = (wid >> 1) * 32;
    const int wn = (wid & 1) * 32;
    const uint32_t aBase = sAu +
        (uint32_t)((wm + (l & 7) + ((l >> 3) & 1) * 8) * AROWB + (((l >> 4) & 1) * 8) * 2);
    const uint32_t bBase = sWu +
        (uint32_t)((wn + (l & 7) + ((l >> 4) & 1) * 8) * AROWB + (((l >> 3) & 1) * 8) * 2);

    const float sc = 0.17677669529663687f;

    for (int nt = 0; nt < Ntiles; nt++) {
        __syncthreads();
        {
            const uint4* wsrc = (const uint4*)Wsp + (size_t)nt * 64 * 48;
#pragma unroll
            for (int t = 0; t < 12; t++) {
                int s = tid + t * 256;
                int row = s / 48, j = s - row * 48;
                *(uint4*)(sm + SM_W_OFF + row * AROWB + j * 16) = wsrc[row * 48 + j];
            }
        }
        __syncthreads();

        float d[2][4][4];
#pragma unroll
        for (int mi = 0; mi < 2; mi++)
#pragma unroll
            for (int ni = 0; ni < 4; ni++)
#pragma unroll
                for (int e = 0; e < 4; e++) d[mi][ni][e] = 0.f;

#pragma unroll
        for (int ph = 0; ph < 3; ph++) {
            const uint32_t ab0 = aBase + (ph == 2 ? 384u : 0u);
            const uint32_t bb0 = bBase + (ph == 1 ? 384u : 0u);
#pragma unroll
            for (int ks = 0; ks < 12; ks++) {
                uint32_t a0[4], a1[4], br0[4], br1[4];
                ldsm_x4(a0, ab0 + ks * 32);
                ldsm_x4(a1, ab0 + ks * 32 + 16 * AROWB);
                ldsm_x4(br0, bb0 + ks * 32);
                ldsm_x4(br1, bb0 + ks * 32 + 16 * AROWB);
                mma_bf16(d[0][0], a0, br0[0], br0[1]);
                mma_bf16(d[0][1], a0, br0[2], br0[3]);
                mma_bf16(d[0][2], a0, br1[0], br1[1]);
                mma_bf16(d[0][3], a0, br1[2], br1[3]);
                mma_bf16(d[1][0], a1, br0[0], br0[1]);
                mma_bf16(d[1][1], a1, br0[2], br0[3]);
                mma_bf16(d[1][2], a1, br1[0], br1[1]);
                mma_bf16(d[1][3], a1, br1[2], br1[3]);
            }
        }

#pragma unroll
        for (int mi = 0; mi < 2; mi++)
#pragma unroll
            for (int ni = 0; ni < 4; ni++) {
                size_t gr = m0 + wm + mi * 16 + (l >> 2);
                int gc = nt * 64 + wn + ni * 8 + (l & 3) * 2;
                float b0v = __ldg(bias + gc), b1v = __ldg(bias + gc + 1);
                float v0 = d[mi][ni][0] + b0v, v1 = d[mi][ni][1] + b1v;
                float v2 = d[mi][ni][2] + b0v, v3 = d[mi][ni][3] + b1v;
                if (do_scale && gc < CDIM) { v0 *= sc; v1 *= sc; v2 *= sc; v3 *= sc; }
                float2 o0; o0.x = v0; o0.y = v1;
                float2 o1; o1.x = v2; o1.y = v3;
                *(float2*)&C[gr * P + gc] = o0;
                *(float2*)&C[(gr + 8) * P + gc] = o1;
            }
    }
}

// ---------------- Register-blocked attention ----------------
// Block = (window, head), 128 thr / 4 warps. Warp w owns i-rows [w*13, ...).
// K columns live in registers (lane j); Q read as float4 broadcasts; softmax
// fused into the QK row loop (warp-local, shuffle reductions); PV with V in
// register chunks and per-row register accumulators.
__global__ __launch_bounds__(128)
void attn_kernel(const float* __restrict__ qkv, const float* __restrict__ mask,
                 const float* __restrict__ bias_h, float* __restrict__ out) {
    __shared__ float q[NTOK][HD];        // pitch 128B
    __shared__ float kt[HD][52];         // transposed K
    __shared__ float v[NTOK][HD];
    __shared__ float s[NTOK][52];        // softmaxed scores, pitch 208B (16B mult)

    const int b = blockIdx.x;
    const int h = blockIdx.y;
    const int tid = threadIdx.x;
    const int wid = tid >> 5, lane = tid & 31;

    // ---- stage q/k/v (float4 gmem loads) ----
    const float* base = qkv + (size_t)b * NTOK * QKVC + h * HD;
    for (int e = tid; e < NTOK * 8; e += 128) {
        int t = e >> 3, d4 = (e & 7) * 4;
        const float* rp = base + (size_t)t * QKVC + d4;
        float4 qv = *(const float4*)rp;
        *(float4*)&q[t][d4] = qv;               // Q pre-scaled in GEMM
        float4 kv = *(const float4*)(rp + CDIM);
        kt[d4 + 0][t] = kv.x;
        kt[d4 + 1][t] = kv.y;
        kt[d4 + 2][t] = kv.z;
        kt[d4 + 3][t] = kv.w;
        float4 vv = *(const float4*)(rp + 2 * CDIM);
        *(float4*)&v[t][d4] = vv;
    }
    __syncthreads();

    const int r0 = wid * 13;
    const int nr = (wid < 3) ? 13 : 10;
    const float* mrow = mask + (size_t)(b & (NWMASK - 1)) * NN;
    const float* bh = bias_h + h * NN;

    // ---- K columns into registers ----
    const int j1 = lane + 32;
    const bool j1v = (j1 < NTOK);
    float kr0[HD], kr1[HD];
#pragma unroll
    for (int d = 0; d < HD; d++) {
        kr0[d] = kt[d][lane];
        kr1[d] = j1v ? kt[d][j1] : 0.f;
    }

    // ---- QK^T + bias + mask + softmax, one row at a time (warp-local) ----
    for (int r = 0; r < nr; r++) {
        const int i = r0 + r;
        float a0 = 0.f, a1 = 0.f;
#pragma unroll
        for (int d4 = 0; d4 < 8; d4++) {
            float4 qv = *(const float4*)&q[i][d4 * 4];   // broadcast
            a0 = fmaf(qv.x, kr0[d4 * 4 + 0], a0);
            a0 = fmaf(qv.y, kr0[d4 * 4 + 1], a0);
            a0 = fmaf(qv.z, kr0[d4 * 4 + 2], a0);
            a0 = fmaf(qv.w, kr0[d4 * 4 + 3], a0);
            a1 = fmaf(qv.x, kr1[d4 * 4 + 0], a1);
            a1 = fmaf(qv.y, kr1[d4 * 4 + 1], a1);
            a1 = fmaf(qv.z, kr1[d4 * 4 + 2], a1);
            a1 = fmaf(qv.w, kr1[d4 * 4 + 3], a1);
        }
        const int p = i * NTOK;
        a0 += __ldg(bh + p + lane) + mrow[p + lane];
        if (j1v) a1 += __ldg(bh + p + j1) + mrow[p + j1];
        else     a1 = -1e30f;

        float mx = fmaxf(a0, a1);
#pragma unroll
        for (int off = 16; off > 0; off >>= 1)
            mx = fmaxf(mx, __shfl_xor_sync(0xFFFFFFFFu, mx, off));
        float e0 = __expf(a0 - mx);
        float e1 = j1v ? __expf(a1 - mx) : 0.f;
        float sum = e0 + e1;
#pragma unroll
        for (int off = 16; off > 0; off >>= 1)
            sum += __shfl_xor_sync(0xFFFFFFFFu, sum, off);
        float inv = 1.f / sum;
        s[i][lane] = e0 * inv;
        if (j1v) s[i][j1] = e1 * inv;
    }

    // ---- PV: V chunks in registers, per-row register accumulators ----
    float acc[13];
#pragma unroll
    for (int r = 0; r < 13; r++) acc[r] = 0.f;

#pragma unroll
    for (int c = 0; c < 3; c++) {
        const int jb = c * 16;
        float vr[16];
#pragma unroll
        for (int jj = 0; jj < 16; jj++) vr[jj] = v[jb + jj][lane];
#pragma unroll
        for (int r = 0; r < 13; r++) {
            if (r < nr) {
                const int i = r0 + r;
#pragma unroll
                for (int k4 = 0; k4 < 4; k4++) {
                    float4 sb = *(const float4*)&s[i][jb + k4 * 4];  // broadcast
                    acc[r] = fmaf(sb.x, vr[k4 * 4 + 0], acc[r]);
                    acc[r] = fmaf(sb.y, vr[k4 * 4 + 1], acc[r]);
                    acc[r] = fmaf(sb.z, vr[k4 * 4 + 2], acc[r]);
                    acc[r] = fmaf(sb.w, vr[k4 * 4 + 3], acc[r]);
                }
            }
        }
    }
    {   // j = 48
        float v48 = v[48][lane];
#pragma unroll
        for (int r = 0; r < 13; r++)
            if (r < nr) acc[r] = fmaf(s[r0 + r][48], v48, acc[r]);
    }

    float* ob = out + ((size_t)b * NTOK) * CDIM + h * HD + lane;
#pragma unroll
    for (int r = 0; r < 13; r++)
        if (r < nr) ob[(size_t)(r0 + r) * CDIM] = acc[r];
}

// ---------------- launch ----------------
extern "C" void kernel_launch(void* const* d_in, const int* in_sizes, int n_in,
                              void* d_out, int out_size) {
    const float* x        = (const float*)d_in[0];  // [8192,7,7,192]
    const float* mask     = (const float*)d_in[1];  // [1024,49,49]
    const float* qkv_w    = (const float*)d_in[2];  // [576,192]
    const float* qkv_b    = (const float*)d_in[3];  // [576]
    const float* proj_w   = (const float*)d_in[4];  // [192,192]
    const float* proj_b   = (const float*)d_in[5];  // [192]
    const float* bias_tab = (const float*)d_in[6];  // [169,6]
    const int*   rel_idx  = (const int*)d_in[7];    // [49,49]
    float* out = (float*)d_out;

    void *qkv_p, *att_p, *wqs_p, *wps_p, *bh_p;
    cudaGetSymbolAddress(&qkv_p, g_qkv);
    cudaGetSymbolAddress(&att_p, g_att);
    cudaGetSymbolAddress(&wqs_p, g_wqs);
    cudaGetSymbolAddress(&wps_p, g_wps);
    cudaGetSymbolAddress(&bh_p, g_biash);
    float* qkv = (float*)qkv_p;
    float* att = (float*)att_p;
    __nv_bfloat16* wqs = (__nv_bfloat16*)wqs_p;
    __nv_bfloat16* wps = (__nv_bfloat16*)wps_p;
    float* biash = (float*)bh_p;

    cudaFuncSetAttribute(gemm_mma, cudaFuncAttributeMaxDynamicSharedMemorySize,
                         SMEM_BYTES);

    // 0) split weights + pre-gather bias
    split_f32_kernel<<<(QKVC * 48 + 255) / 256, 256>>>(qkv_w, wqs, QKVC * 48);
    split_f32_kernel<<<(CDIM * 48 + 255) / 256, 256>>>(proj_w, wps, CDIM * 48);
    bias_expand_kernel<<<(HEADS * NN + 255) / 256, 256>>>(bias_tab, rel_idx, biash);

    // 1) QKV projection (+bias, fold Q scale)
    gemm_mma<<<MROWS / 128, 256, SMEM_BYTES>>>(x, wqs, qkv_b, qkv, 9, 1);

    // 2) Window attention (register-blocked fp32)
    {
        dim3 g(BWIN, HEADS);
        attn_kernel<<<g, 128>>>(qkv, mask, biash, att);
    }

    // 3) Output projection -> d_out
    gemm_mma<<<MROWS / 128, 256, SMEM_BYTES>>>(att, wps, proj_b, out, 3, 0);
}